// round 5
// baseline (speedup 1.0000x reference)
#include <cuda_runtime.h>

// Reference semantics after dead-code elimination:
//   r  = eye(3)                       (unconditional overwrite in reference)
//   tb = -mean(mkpts0, axis=1)        ( = -r @ src_mean with r = I )
// Output: 12 floats = [r row-major (9), tb (3)].
//
// Single-CTA version: grid=1, 768 threads = 3 row-groups x 256 threads.
// Eliminates cross-CTA completion spread (3 CTAs on different SMs/L2 dies).

#define ROWLEN   8192
#define TPR      256                 // threads per row
#define TPB      (3 * TPR)           // 768
#define LD       (ROWLEN / 4 / TPR)  // 8 float4 per thread
#define NWARPS   (TPB / 32)          // 24
#define INV_NEG  (-1.0f / 8192.0f)   // exact: power-of-two divisor

__global__ void __launch_bounds__(TPB, 1)
svdhead_kernel(const float* __restrict__ mkpts0, float* __restrict__ out) {
    const int t   = threadIdx.x;
    const int row = t >> 8;          // 0..2
    const int rt  = t & (TPR - 1);   // 0..255 within row

    // Identity write (indices 0..8) overlaps the load latency.
    if (t < 9) {
        out[t] = ((t & 3) == 0) ? 1.0f : 0.0f;   // t = 0,4,8 -> 1
    }

    // Row has 2048 float4; 256 threads x 8 fully-unrolled LDG.128, all in
    // flight at once -> one DRAM round trip for the whole block.
    const float4* row4 = reinterpret_cast<const float4*>(mkpts0)
                       + (size_t)row * (ROWLEN / 4) + rt;
    float4 v[LD];
    #pragma unroll
    for (int i = 0; i < LD; i++) v[i] = row4[i * TPR];

    // Depth-5 pairwise FADD tree over the 32 scalars.
    float p[LD];
    #pragma unroll
    for (int i = 0; i < LD; i++) p[i] = (v[i].x + v[i].y) + (v[i].z + v[i].w);
    float sum = ((p[0] + p[1]) + (p[2] + p[3])) + ((p[4] + p[5]) + (p[6] + p[7]));

    // Warp tree reduce: 5 shfl. (Each warp is entirely within one row.)
    #pragma unroll
    for (int off = 16; off > 0; off >>= 1)
        sum += __shfl_xor_sync(0xFFFFFFFFu, sum, off);

    __shared__ float warp_sums[NWARPS];
    if ((t & 31) == 0) warp_sums[t >> 5] = sum;
    __syncthreads();

    // Threads 0..23 (all in warp 0): warp_sums[0..7]=row0, [8..15]=row1,
    // [16..23]=row2. Fold each group of 8 with 3 xor-shfls (xor<8 stays
    // within the group), then leaders write.
    if (t < NWARPS) {
        float s = warp_sums[t];
        #pragma unroll
        for (int off = 4; off > 0; off >>= 1)
            s += __shfl_xor_sync(0x00FFFFFFu, s, off);
        if ((t & 7) == 0)
            out[9 + (t >> 3)] = s * INV_NEG;
    }
}

extern "C" void kernel_launch(void* const* d_in, const int* in_sizes, int n_in,
                              void* d_out, int out_size) {
    const float* mkpts0 = (const float*)d_in[0];
    float* out = (float*)d_out;
    svdhead_kernel<<<1, TPB>>>(mkpts0, out);
}